// round 8
// baseline (speedup 1.0000x reference)
#include <cuda_runtime.h>
#include <cuda_bf16.h>
#include <math.h>

#define N_NODES 50000
#define N_EDGES 600000
#define N_GRAPHS 64
#define SCAN_BLOCKS ((N_NODES + 1023) / 1024)   // 49

// ------------------- scratch (no allocation allowed) -------------------
__device__ float g_T[N_NODES * 128];     // GEMM output (transformed features)
__device__ float g_H[N_NODES * 128];     // aggregated layer output / next input
__device__ float g_dinv[N_NODES];
__device__ int   g_deg[N_NODES];
__device__ int   g_off[N_NODES + 1];
__device__ int   g_cur[N_NODES];
__device__ int   g_ebuf[N_EDGES];        // CSR: source row per slot (by destination)
__device__ int   g_bsum[64];             // scan block sums
__device__ float g_pool[N_GRAPHS * 64];
__device__ int   g_cnt[N_GRAPHS];
__device__ float g_fc1[N_GRAPHS * 32];

// ------------------- zero init -------------------
__global__ void zero_kernel() {
    int i = blockIdx.x * blockDim.x + threadIdx.x;
    if (i < N_NODES) { g_deg[i] = 0; g_cur[i] = 0; }
    if (i < N_GRAPHS * 64) g_pool[i] = 0.f;
    if (i < N_GRAPHS) g_cnt[i] = 0;
}

// ------------------- CSR build (edge_index is int32) -------------------
__global__ void count_kernel(const int* __restrict__ ei) {
    int e = blockIdx.x * blockDim.x + threadIdx.x;
    if (e < N_EDGES) {
        int c = ei[N_EDGES + e];
        if (c >= 0 && c < N_NODES) atomicAdd(&g_deg[c], 1);
    }
}

// ---- parallel exclusive scan of g_deg -> g_off (3 kernels) ----
__global__ __launch_bounds__(1024) void scan1_kernel() {
    __shared__ int wsum[32];
    int tid = threadIdx.x;
    int i = blockIdx.x * 1024 + tid;
    int lane = tid & 31, warp = tid >> 5;
    int v = (i < N_NODES) ? g_deg[i] : 0;
    int x = v;
    #pragma unroll
    for (int d = 1; d < 32; d <<= 1) {
        int t = __shfl_up_sync(0xFFFFFFFFu, x, d);
        if (lane >= d) x += t;
    }
    if (lane == 31) wsum[warp] = x;
    __syncthreads();
    if (tid < 32) {
        int w = wsum[tid];
        #pragma unroll
        for (int d = 1; d < 32; d <<= 1) {
            int t = __shfl_up_sync(0xFFFFFFFFu, w, d);
            if (tid >= d) w += t;
        }
        wsum[tid] = w;
    }
    __syncthreads();
    int excl = x - v + (warp ? wsum[warp - 1] : 0);
    if (i < N_NODES) g_off[i] = excl;
    if (tid == 0) g_bsum[blockIdx.x] = wsum[31];
}

__global__ void scan2_kernel() {   // 1 block, 64 threads
    __shared__ int ws[2];
    int tid = threadIdx.x, lane = tid & 31, warp = tid >> 5;
    int v = (tid < SCAN_BLOCKS) ? g_bsum[tid] : 0;
    int x = v;
    #pragma unroll
    for (int d = 1; d < 32; d <<= 1) {
        int t = __shfl_up_sync(0xFFFFFFFFu, x, d);
        if (lane >= d) x += t;
    }
    if (lane == 31) ws[warp] = x;
    __syncthreads();
    int excl = x - v + (warp ? ws[0] : 0);
    if (tid < SCAN_BLOCKS) g_bsum[tid] = excl;
    if (tid == SCAN_BLOCKS - 1) g_off[N_NODES] = excl + v;   // == N_EDGES
}

__global__ __launch_bounds__(1024) void scan3_kernel() {   // add offsets + dinv
    int i = blockIdx.x * 1024 + threadIdx.x;
    if (i < N_NODES) {
        g_off[i] += g_bsum[blockIdx.x];
        g_dinv[i] = rsqrtf((float)(g_deg[i] + 1));  // +1 self loop
    }
}

__global__ void fill_kernel(const int* __restrict__ ei) {
    int e = blockIdx.x * blockDim.x + threadIdx.x;
    if (e < N_EDGES) {
        int c = ei[N_EDGES + e];
        int r = ei[e];
        if (c >= 0 && c < N_NODES && r >= 0 && r < N_NODES) {
            int p = atomicAdd(&g_cur[c], 1);
            g_ebuf[g_off[c] + p] = r;
        }
    }
}

// ------------------- GEMM: g_T = act(src) @ W  (src:[n,128], W:[128,FOUT])
// 64-row M tile per block, full-K X staging, W in 32-row k-tiles.
template <int FOUT, bool RELU_IN, bool SRC_EXT>
__global__ __launch_bounds__(256) void gemm_kernel(
    const float* __restrict__ X, const float* __restrict__ W, int n)
{
    constexpr int TN = FOUT / 32;  // 4 or 2 cols per thread
    __shared__ float Xs[64 * 128];         // 32 KB
    __shared__ float Ws[32 * FOUT];        // 16 KB (FOUT=128) / 8 KB
    const float* __restrict__ src = SRC_EXT ? X : (const float*)g_H;
    int m0 = blockIdx.x * 64;
    int t = threadIdx.x;
    int lane = t & 31, warp = t >> 5;

    // stage X tile: 2048 float4, 8 per thread (relu fused)
    #pragma unroll
    for (int i = 0; i < 8; i++) {
        int idx = t + i * 256;          // float4 index
        int row = idx >> 5;             // 32 float4 per row
        int c4  = idx & 31;
        int gr  = m0 + row;
        float4 v = make_float4(0.f, 0.f, 0.f, 0.f);
        if (gr < n) v = *(const float4*)&src[(size_t)gr * 128 + c4 * 4];
        if (RELU_IN) {
            v.x = fmaxf(v.x, 0.f); v.y = fmaxf(v.y, 0.f);
            v.z = fmaxf(v.z, 0.f); v.w = fmaxf(v.w, 0.f);
        }
        *(float4*)&Xs[row * 128 + c4 * 4] = v;
    }

    float acc[8][TN];
    #pragma unroll
    for (int r = 0; r < 8; r++)
        #pragma unroll
        for (int c = 0; c < TN; c++) acc[r][c] = 0.f;

    #pragma unroll
    for (int kt = 0; kt < 4; kt++) {
        // stage W k-tile: 32 x FOUT
        constexpr int NW4 = 32 * FOUT / 4;   // float4 count: 1024 or 512
        #pragma unroll
        for (int i = 0; i < NW4 / 256; i++) {
            int idx = t + i * 256;
            int kk = idx / (FOUT / 4);
            int c4 = idx % (FOUT / 4);
            *(float4*)&Ws[kk * FOUT + c4 * 4] =
                *(const float4*)&W[(size_t)(kt * 32 + kk) * FOUT + c4 * 4];
        }
        __syncthreads();
        #pragma unroll 8
        for (int kk = 0; kk < 32; kk++) {
            float wv[TN];
            if (TN == 4) {
                float4 w4 = *(float4*)&Ws[kk * FOUT + lane * 4];
                wv[0] = w4.x; wv[1] = w4.y; wv[2 % TN] = w4.z; wv[3 % TN] = w4.w;
            } else {
                float2 w2 = *(float2*)&Ws[kk * FOUT + lane * 2];
                wv[0] = w2.x; wv[1] = w2.y;
            }
            #pragma unroll
            for (int r = 0; r < 8; r++) {
                float xv = Xs[(warp * 8 + r) * 128 + kt * 32 + kk];
                #pragma unroll
                for (int c = 0; c < TN; c++) acc[r][c] += xv * wv[c];
            }
        }
        __syncthreads();
    }

    #pragma unroll
    for (int r = 0; r < 8; r++) {
        int gr = m0 + warp * 8 + r;
        if (gr < n) {
            if (TN == 4) {
                float4 v = make_float4(acc[r][0], acc[r][1], acc[r][2 % TN], acc[r][3 % TN]);
                *(float4*)&g_T[(size_t)gr * FOUT + lane * 4] = v;
            } else {
                float2 v = make_float2(acc[r][0], acc[r][1]);
                *(float2*)&g_T[(size_t)gr * FOUT + lane * 2] = v;
            }
        }
    }
}

// ------------------- Aggregation: g_H[i] = b + dinv_i^2*T[i] + sum_e dinv_r*dinv_i*T[r]
template <int F>
__global__ __launch_bounds__(256) void agg_kernel(const float* __restrict__ bias)
{
    int i = (blockIdx.x * blockDim.x + threadIdx.x) >> 5;
    if (i >= N_NODES) return;
    int lane = threadIdx.x & 31;
    constexpr int V = F / 32;  // 4 or 2
    float dii = g_dinv[i];
    float acc[V];
    {
        const float* Ti = g_T + (size_t)i * F + lane * V;
        float dii2 = dii * dii;
        #pragma unroll
        for (int c = 0; c < V; c++) acc[c] = bias[lane * V + c] + dii2 * Ti[c];
    }
    int s = g_off[i], e = g_off[i + 1];
    int p = s;
    for (; p + 2 <= e; p += 2) {
        int r0 = g_ebuf[p], r1 = g_ebuf[p + 1];
        float w0 = dii * g_dinv[r0], w1 = dii * g_dinv[r1];
        const float* T0 = g_T + (size_t)r0 * F + lane * V;
        const float* T1 = g_T + (size_t)r1 * F + lane * V;
        if (V == 4) {
            float4 a = *(const float4*)T0;
            float4 b = *(const float4*)T1;
            acc[0] += w0 * a.x; acc[1] += w0 * a.y;
            acc[2 % V] += w0 * a.z; acc[3 % V] += w0 * a.w;
            acc[0] += w1 * b.x; acc[1] += w1 * b.y;
            acc[2 % V] += w1 * b.z; acc[3 % V] += w1 * b.w;
        } else {
            float2 a = *(const float2*)T0;
            float2 b = *(const float2*)T1;
            acc[0] += w0 * a.x; acc[1] += w0 * a.y;
            acc[0] += w1 * b.x; acc[1] += w1 * b.y;
        }
    }
    if (p < e) {
        int r = g_ebuf[p];
        float w = dii * g_dinv[r];
        const float* Tr = g_T + (size_t)r * F + lane * V;
        if (V == 4) {
            float4 a = *(const float4*)Tr;
            acc[0] += w * a.x; acc[1] += w * a.y;
            acc[2 % V] += w * a.z; acc[3 % V] += w * a.w;
        } else {
            float2 a = *(const float2*)Tr;
            acc[0] += w * a.x; acc[1] += w * a.y;
        }
    }
    float* Hi = g_H + (size_t)i * F + lane * V;
    #pragma unroll
    for (int c = 0; c < V; c++) Hi[c] = acc[c];
}

// ------------------- mean pool over sorted batch ids (input relu'd here) -----
__global__ void pool_kernel(const int* __restrict__ batch)
{
    int c = threadIdx.x & 63;   // channel
    int sub = threadIdx.x >> 6; // 0..3
    int n0 = blockIdx.x * 512;
    float acc = 0.f; int cur = -1; int cnt = 0;
    for (int j = sub; j < 512; j += 4) {
        int node = n0 + j;
        if (node >= N_NODES) break;
        int b = batch[node];
        if (b < 0 || b >= N_GRAPHS) continue;
        if (b != cur) {
            if (cur >= 0) {
                atomicAdd(&g_pool[cur * 64 + c], acc);
                if (c == 0) atomicAdd(&g_cnt[cur], cnt);
            }
            cur = b; acc = 0.f; cnt = 0;
        }
        acc += fmaxf(g_H[(size_t)node * 64 + c], 0.f);
        cnt++;
    }
    if (cur >= 0) {
        atomicAdd(&g_pool[cur * 64 + c], acc);
        if (c == 0) atomicAdd(&g_cnt[cur], cnt);
    }
}

// ------------------- tiny MLP head -------------------
__global__ void fc1_kernel(const float* __restrict__ Wf1, const float* __restrict__ bf1) {
    int g = blockIdx.x; int j = threadIdx.x;  // grid 64, block 32
    float inv = 1.f / fmaxf((float)g_cnt[g], 1.f);
    float s = bf1[j];
    for (int k = 0; k < 64; k++) s += g_pool[g * 64 + k] * inv * Wf1[k * 32 + j];
    g_fc1[g * 32 + j] = fmaxf(s, 0.f);
}

__global__ void fc2_kernel(const float* __restrict__ Wf2, const float* __restrict__ bf2,
                           float* __restrict__ out) {
    int g = blockIdx.x; int o = threadIdx.x;  // grid 64, block 10
    float s = bf2[o];
    for (int j = 0; j < 32; j++) s += g_fc1[g * 32 + j] * Wf2[j * 10 + o];
    out[g * 10 + o] = s;
}

// ------------------- launch: kernel launches ONLY, no other CUDA API --------
extern "C" void kernel_launch(void* const* d_in, const int* in_sizes, int n_in,
                              void* d_out, int out_size)
{
    const float* x     = (const float*)d_in[0];
    const int*   ei    = (const int*)d_in[1];
    const int*   batch = (const int*)d_in[2];
    const float* W1  = (const float*)d_in[3];
    const float* b1  = (const float*)d_in[4];
    const float* W2  = (const float*)d_in[5];
    const float* b2  = (const float*)d_in[6];
    const float* W3  = (const float*)d_in[7];
    const float* b3  = (const float*)d_in[8];
    const float* Wf1 = (const float*)d_in[9];
    const float* bf1 = (const float*)d_in[10];
    const float* Wf2 = (const float*)d_in[11];
    const float* bf2 = (const float*)d_in[12];
    float* out = (float*)d_out;

    zero_kernel<<<(N_NODES + 255) / 256, 256>>>();

    // CSR build
    count_kernel<<<(N_EDGES + 255) / 256, 256>>>(ei);
    scan1_kernel<<<SCAN_BLOCKS, 1024>>>();
    scan2_kernel<<<1, 64>>>();
    scan3_kernel<<<SCAN_BLOCKS, 1024>>>();
    fill_kernel<<<(N_EDGES + 255) / 256, 256>>>(ei);

    int gemm_blocks = (N_NODES + 63) / 64;
    int agg_blocks  = (N_NODES * 32 + 255) / 256;

    // layer 1: 128 -> 128 (external input)
    gemm_kernel<128, false, true><<<gemm_blocks, 256>>>(x, W1, N_NODES);
    agg_kernel<128><<<agg_blocks, 256>>>(b1);
    // layer 2: 128 -> 128 (g_H input, relu)
    gemm_kernel<128, true, false><<<gemm_blocks, 256>>>(nullptr, W2, N_NODES);
    agg_kernel<128><<<agg_blocks, 256>>>(b2);
    // layer 3: 128 -> 64 (g_H input, relu)
    gemm_kernel<64, true, false><<<gemm_blocks, 256>>>(nullptr, W3, N_NODES);
    agg_kernel<64><<<agg_blocks, 256>>>(b3);

    // mean pool (relu fused) + MLP head
    pool_kernel<<<(N_NODES + 511) / 512, 256>>>(batch);
    fc1_kernel<<<N_GRAPHS, 32>>>(Wf1, bf1);
    fc2_kernel<<<N_GRAPHS, 10>>>(Wf2, bf2, out);
}

// round 9
// speedup vs baseline: 1.4724x; 1.4724x over previous
#include <cuda_runtime.h>
#include <cuda_bf16.h>
#include <math.h>

#define N_NODES 50000
#define N_EDGES 600000
#define N_GRAPHS 64
#define SCAN_BLOCKS ((N_NODES + 1023) / 1024)   // 49

// ------------------- scratch (no allocation allowed) -------------------
__device__ float g_T[N_NODES * 128];     // GEMM output (transformed features)
__device__ float g_H[N_NODES * 128];     // aggregated layer output / next input
__device__ float g_dinv[N_NODES];
__device__ int   g_deg[N_NODES];
__device__ int   g_off[N_NODES + 1];
__device__ int   g_cur[N_NODES];
__device__ int   g_ebuf[N_EDGES];        // CSR: source row per slot (by destination)
__device__ int   g_bsum[64];             // scan block sums
__device__ float g_pool[N_GRAPHS * 64];
__device__ int   g_cnt[N_GRAPHS];
__device__ float g_fc1[N_GRAPHS * 32];

// ------------------- zero init -------------------
__global__ void zero_kernel() {
    int i = blockIdx.x * blockDim.x + threadIdx.x;
    if (i < N_NODES) { g_deg[i] = 0; g_cur[i] = 0; }
    if (i < N_GRAPHS * 64) g_pool[i] = 0.f;
    if (i < N_GRAPHS) g_cnt[i] = 0;
}

// ------------------- CSR build (edge_index is int32) -------------------
__global__ void count_kernel(const int* __restrict__ ei) {
    int e = blockIdx.x * blockDim.x + threadIdx.x;
    if (e < N_EDGES) {
        int c = ei[N_EDGES + e];
        if (c >= 0 && c < N_NODES) atomicAdd(&g_deg[c], 1);
    }
}

// ---- parallel exclusive scan of g_deg -> g_off (3 kernels) ----
__global__ __launch_bounds__(1024) void scan1_kernel() {
    __shared__ int wsum[32];
    int tid = threadIdx.x;
    int i = blockIdx.x * 1024 + tid;
    int lane = tid & 31, warp = tid >> 5;
    int v = (i < N_NODES) ? g_deg[i] : 0;
    int x = v;
    #pragma unroll
    for (int d = 1; d < 32; d <<= 1) {
        int t = __shfl_up_sync(0xFFFFFFFFu, x, d);
        if (lane >= d) x += t;
    }
    if (lane == 31) wsum[warp] = x;
    __syncthreads();
    if (tid < 32) {
        int w = wsum[tid];
        #pragma unroll
        for (int d = 1; d < 32; d <<= 1) {
            int t = __shfl_up_sync(0xFFFFFFFFu, w, d);
            if (tid >= d) w += t;
        }
        wsum[tid] = w;
    }
    __syncthreads();
    int excl = x - v + (warp ? wsum[warp - 1] : 0);
    if (i < N_NODES) g_off[i] = excl;
    if (tid == 0) g_bsum[blockIdx.x] = wsum[31];
}

__global__ void scan2_kernel() {   // 1 block, 64 threads
    __shared__ int ws[2];
    int tid = threadIdx.x, lane = tid & 31, warp = tid >> 5;
    int v = (tid < SCAN_BLOCKS) ? g_bsum[tid] : 0;
    int x = v;
    #pragma unroll
    for (int d = 1; d < 32; d <<= 1) {
        int t = __shfl_up_sync(0xFFFFFFFFu, x, d);
        if (lane >= d) x += t;
    }
    if (lane == 31) ws[warp] = x;
    __syncthreads();
    int excl = x - v + (warp ? ws[0] : 0);
    if (tid < SCAN_BLOCKS) g_bsum[tid] = excl;
    if (tid == SCAN_BLOCKS - 1) g_off[N_NODES] = excl + v;   // == N_EDGES
}

__global__ __launch_bounds__(1024) void scan3_kernel() {   // add offsets + dinv
    int i = blockIdx.x * 1024 + threadIdx.x;
    if (i < N_NODES) {
        g_off[i] += g_bsum[blockIdx.x];
        g_dinv[i] = rsqrtf((float)(g_deg[i] + 1));  // +1 self loop
    }
}

__global__ void fill_kernel(const int* __restrict__ ei) {
    int e = blockIdx.x * blockDim.x + threadIdx.x;
    if (e < N_EDGES) {
        int c = ei[N_EDGES + e];
        int r = ei[e];
        if (c >= 0 && c < N_NODES && r >= 0 && r < N_NODES) {
            int p = atomicAdd(&g_cur[c], 1);
            g_ebuf[g_off[c] + p] = r;
        }
    }
}

// ------------------- GEMM: g_T = act(src) @ W  (src:[n,128], W:[128,FOUT])
// k-tiled (32), Xs[64][33] low-smem (24.4KB total for FOUT=128) -> full occupancy.
// W smem read via float4 (conflict-free LDS.128) — the one R8 element kept.
template <int FOUT, bool RELU_IN, bool SRC_EXT>
__global__ __launch_bounds__(256) void gemm_kernel(
    const float* __restrict__ X, const float* __restrict__ W, int n)
{
    constexpr int TN = FOUT / 32;  // 4 or 2 cols per thread
    __shared__ float Xs[64][33];
    __shared__ float Ws[32 * FOUT];
    const float* __restrict__ src = SRC_EXT ? X : (const float*)g_H;
    int m0 = blockIdx.x * 64;
    int t = threadIdx.x;
    int lane = t & 31, warp = t >> 5;   // warp 0..7

    float acc[8][TN];
    #pragma unroll
    for (int r = 0; r < 8; r++)
        #pragma unroll
        for (int c = 0; c < TN; c++) acc[r][c] = 0.f;

    #pragma unroll
    for (int kt = 0; kt < 4; kt++) {
        // stage X k-tile: rows warp*8..warp*8+7, col = lane
        #pragma unroll
        for (int j = 0; j < 8; j++) {
            int r = warp * 8 + j;
            int gr = m0 + r;
            float v = (gr < n) ? src[(size_t)gr * 128 + kt * 32 + lane] : 0.f;
            if (RELU_IN) v = fmaxf(v, 0.f);
            Xs[r][lane] = v;
        }
        // stage W k-tile: 32 x FOUT
        constexpr int NW4 = 32 * FOUT / 4;   // 1024 (FOUT=128) or 512
        #pragma unroll
        for (int i = 0; i < NW4 / 256; i++) {
            int idx = t + i * 256;
            int kk = idx / (FOUT / 4);
            int c4 = idx % (FOUT / 4);
            *(float4*)&Ws[kk * FOUT + c4 * 4] =
                *(const float4*)&W[(size_t)(kt * 32 + kk) * FOUT + c4 * 4];
        }
        __syncthreads();
        #pragma unroll 8
        for (int kk = 0; kk < 32; kk++) {
            float wv[TN];
            if (TN == 4) {
                float4 w4 = *(float4*)&Ws[kk * FOUT + lane * 4];
                wv[0] = w4.x; wv[1] = w4.y; wv[2 % TN] = w4.z; wv[3 % TN] = w4.w;
            } else {
                float2 w2 = *(float2*)&Ws[kk * FOUT + lane * 2];
                wv[0] = w2.x; wv[1] = w2.y;
            }
            #pragma unroll
            for (int r = 0; r < 8; r++) {
                float xv = Xs[warp * 8 + r][kk];
                #pragma unroll
                for (int c = 0; c < TN; c++) acc[r][c] += xv * wv[c];
            }
        }
        __syncthreads();
    }

    #pragma unroll
    for (int r = 0; r < 8; r++) {
        int gr = m0 + warp * 8 + r;
        if (gr < n) {
            if (TN == 4) {
                float4 v = make_float4(acc[r][0], acc[r][1], acc[r][2 % TN], acc[r][3 % TN]);
                *(float4*)&g_T[(size_t)gr * FOUT + lane * 4] = v;
            } else {
                float2 v = make_float2(acc[r][0], acc[r][1]);
                *(float2*)&g_T[(size_t)gr * FOUT + lane * 2] = v;
            }
        }
    }
}

// ------------------- Aggregation: g_H[i] = b + dinv_i^2*T[i] + sum_e dinv_r*dinv_i*T[r]
template <int F>
__global__ __launch_bounds__(256) void agg_kernel(const float* __restrict__ bias)
{
    int i = (blockIdx.x * blockDim.x + threadIdx.x) >> 5;
    if (i >= N_NODES) return;
    int lane = threadIdx.x & 31;
    constexpr int V = F / 32;  // 4 or 2
    float dii = g_dinv[i];
    float acc[V];
    {
        const float* Ti = g_T + (size_t)i * F + lane * V;
        float dii2 = dii * dii;
        #pragma unroll
        for (int c = 0; c < V; c++) acc[c] = bias[lane * V + c] + dii2 * Ti[c];
    }
    int s = g_off[i], e = g_off[i + 1];
    int p = s;
    for (; p + 2 <= e; p += 2) {
        int r0 = g_ebuf[p], r1 = g_ebuf[p + 1];
        float w0 = dii * g_dinv[r0], w1 = dii * g_dinv[r1];
        const float* T0 = g_T + (size_t)r0 * F + lane * V;
        const float* T1 = g_T + (size_t)r1 * F + lane * V;
        if (V == 4) {
            float4 a = *(const float4*)T0;
            float4 b = *(const float4*)T1;
            acc[0] += w0 * a.x; acc[1] += w0 * a.y;
            acc[2 % V] += w0 * a.z; acc[3 % V] += w0 * a.w;
            acc[0] += w1 * b.x; acc[1] += w1 * b.y;
            acc[2 % V] += w1 * b.z; acc[3 % V] += w1 * b.w;
        } else {
            float2 a = *(const float2*)T0;
            float2 b = *(const float2*)T1;
            acc[0] += w0 * a.x; acc[1] += w0 * a.y;
            acc[0] += w1 * b.x; acc[1] += w1 * b.y;
        }
    }
    if (p < e) {
        int r = g_ebuf[p];
        float w = dii * g_dinv[r];
        const float* Tr = g_T + (size_t)r * F + lane * V;
        if (V == 4) {
            float4 a = *(const float4*)Tr;
            acc[0] += w * a.x; acc[1] += w * a.y;
            acc[2 % V] += w * a.z; acc[3 % V] += w * a.w;
        } else {
            float2 a = *(const float2*)Tr;
            acc[0] += w * a.x; acc[1] += w * a.y;
        }
    }
    float* Hi = g_H + (size_t)i * F + lane * V;
    #pragma unroll
    for (int c = 0; c < V; c++) Hi[c] = acc[c];
}

// ------------------- mean pool over sorted batch ids (input relu'd here) -----
__global__ void pool_kernel(const int* __restrict__ batch)
{
    int c = threadIdx.x & 63;   // channel
    int sub = threadIdx.x >> 6; // 0..3
    int n0 = blockIdx.x * 512;
    float acc = 0.f; int cur = -1; int cnt = 0;
    for (int j = sub; j < 512; j += 4) {
        int node = n0 + j;
        if (node >= N_NODES) break;
        int b = batch[node];
        if (b < 0 || b >= N_GRAPHS) continue;
        if (b != cur) {
            if (cur >= 0) {
                atomicAdd(&g_pool[cur * 64 + c], acc);
                if (c == 0) atomicAdd(&g_cnt[cur], cnt);
            }
            cur = b; acc = 0.f; cnt = 0;
        }
        acc += fmaxf(g_H[(size_t)node * 64 + c], 0.f);
        cnt++;
    }
    if (cur >= 0) {
        atomicAdd(&g_pool[cur * 64 + c], acc);
        if (c == 0) atomicAdd(&g_cnt[cur], cnt);
    }
}

// ------------------- tiny MLP head -------------------
__global__ void fc1_kernel(const float* __restrict__ Wf1, const float* __restrict__ bf1) {
    int g = blockIdx.x; int j = threadIdx.x;  // grid 64, block 32
    float inv = 1.f / fmaxf((float)g_cnt[g], 1.f);
    float s = bf1[j];
    for (int k = 0; k < 64; k++) s += g_pool[g * 64 + k] * inv * Wf1[k * 32 + j];
    g_fc1[g * 32 + j] = fmaxf(s, 0.f);
}

__global__ void fc2_kernel(const float* __restrict__ Wf2, const float* __restrict__ bf2,
                           float* __restrict__ out) {
    int g = blockIdx.x; int o = threadIdx.x;  // grid 64, block 10
    float s = bf2[o];
    for (int j = 0; j < 32; j++) s += g_fc1[g * 32 + j] * Wf2[j * 10 + o];
    out[g * 10 + o] = s;
}

// ------------------- launch: kernel launches ONLY, no other CUDA API --------
extern "C" void kernel_launch(void* const* d_in, const int* in_sizes, int n_in,
                              void* d_out, int out_size)
{
    const float* x     = (const float*)d_in[0];
    const int*   ei    = (const int*)d_in[1];
    const int*   batch = (const int*)d_in[2];
    const float* W1  = (const float*)d_in[3];
    const float* b1  = (const float*)d_in[4];
    const float* W2  = (const float*)d_in[5];
    const float* b2  = (const float*)d_in[6];
    const float* W3  = (const float*)d_in[7];
    const float* b3  = (const float*)d_in[8];
    const float* Wf1 = (const float*)d_in[9];
    const float* bf1 = (const float*)d_in[10];
    const float* Wf2 = (const float*)d_in[11];
    const float* bf2 = (const float*)d_in[12];
    float* out = (float*)d_out;

    zero_kernel<<<(N_NODES + 255) / 256, 256>>>();

    // CSR build
    count_kernel<<<(N_EDGES + 255) / 256, 256>>>(ei);
    scan1_kernel<<<SCAN_BLOCKS, 1024>>>();
    scan2_kernel<<<1, 64>>>();
    scan3_kernel<<<SCAN_BLOCKS, 1024>>>();
    fill_kernel<<<(N_EDGES + 255) / 256, 256>>>(ei);

    int gemm_blocks = (N_NODES + 63) / 64;
    int agg_blocks  = (N_NODES * 32 + 255) / 256;

    // layer 1: 128 -> 128 (external input)
    gemm_kernel<128, false, true><<<gemm_blocks, 256>>>(x, W1, N_NODES);
    agg_kernel<128><<<agg_blocks, 256>>>(b1);
    // layer 2: 128 -> 128 (g_H input, relu)
    gemm_kernel<128, true, false><<<gemm_blocks, 256>>>(nullptr, W2, N_NODES);
    agg_kernel<128><<<agg_blocks, 256>>>(b2);
    // layer 3: 128 -> 64 (g_H input, relu)
    gemm_kernel<64, true, false><<<gemm_blocks, 256>>>(nullptr, W3, N_NODES);
    agg_kernel<64><<<agg_blocks, 256>>>(b3);

    // mean pool (relu fused) + MLP head
    pool_kernel<<<(N_NODES + 511) / 512, 256>>>(batch);
    fc1_kernel<<<N_GRAPHS, 32>>>(Wf1, bf1);
    fc2_kernel<<<N_GRAPHS, 10>>>(Wf2, bf2, out);
}

// round 13
// speedup vs baseline: 1.5951x; 1.0833x over previous
#include <cuda_runtime.h>
#include <cuda_bf16.h>
#include <math.h>
#include <stdint.h>

#define N_NODES 50000
#define N_EDGES 600000
#define N_GRAPHS 64
#define SCAN_BLOCKS ((N_NODES + 1023) / 1024)   // 49

// ------------------- scratch (no allocation allowed) -------------------
__device__ float g_T[N_NODES * 128];     // GEMM output (transformed features)
__device__ float g_H[N_NODES * 128];     // aggregated layer output / next input
__device__ float g_dinv[N_NODES];
__device__ int   g_deg[N_NODES];
__device__ int   g_off[N_NODES + 1];
__device__ int   g_cur[N_NODES];
__device__ int   g_ebuf[N_EDGES];        // CSR: source row per slot (by destination)
__device__ int   g_bsum[64];             // scan block sums
__device__ float g_pool[N_GRAPHS * 64];
__device__ int   g_cnt[N_GRAPHS];
__device__ float g_fc1[N_GRAPHS * 32];
// split weights, transposed to [n][k] bf16 (hi/mid)
__device__ __nv_bfloat16 g_Wh[3][128 * 128];
__device__ __nv_bfloat16 g_Wm[3][128 * 128];

// ------------------- zero init -------------------
__global__ void zero_kernel() {
    int i = blockIdx.x * blockDim.x + threadIdx.x;
    if (i < N_NODES) { g_deg[i] = 0; g_cur[i] = 0; }
    if (i < N_GRAPHS * 64) g_pool[i] = 0.f;
    if (i < N_GRAPHS) g_cnt[i] = 0;
}

// ------------------- weight split + transpose: g_W*[l][n*128+k] ------------
__global__ void prep_w_kernel(const float* __restrict__ W1,
                              const float* __restrict__ W2,
                              const float* __restrict__ W3) {
    int t = blockIdx.x * blockDim.x + threadIdx.x;   // 16384 threads
    if (t >= 128 * 128) return;
    int n = t >> 7, k = t & 127;
    float v1 = W1[k * 128 + n];
    __nv_bfloat16 h1 = __float2bfloat16(v1);
    g_Wh[0][n * 128 + k] = h1;
    g_Wm[0][n * 128 + k] = __float2bfloat16(v1 - __bfloat162float(h1));
    float v2 = W2[k * 128 + n];
    __nv_bfloat16 h2 = __float2bfloat16(v2);
    g_Wh[1][n * 128 + k] = h2;
    g_Wm[1][n * 128 + k] = __float2bfloat16(v2 - __bfloat162float(h2));
    if (n < 64) {
        float v3 = W3[k * 64 + n];
        __nv_bfloat16 h3 = __float2bfloat16(v3);
        g_Wh[2][n * 128 + k] = h3;
        g_Wm[2][n * 128 + k] = __float2bfloat16(v3 - __bfloat162float(h3));
    }
}

// ------------------- CSR build (edge_index is int32) -------------------
__global__ void count_kernel(const int* __restrict__ ei) {
    int e = blockIdx.x * blockDim.x + threadIdx.x;
    if (e < N_EDGES) {
        int c = ei[N_EDGES + e];
        if (c >= 0 && c < N_NODES) atomicAdd(&g_deg[c], 1);
    }
}

__global__ __launch_bounds__(1024) void scan1_kernel() {
    __shared__ int wsum[32];
    int tid = threadIdx.x;
    int i = blockIdx.x * 1024 + tid;
    int lane = tid & 31, warp = tid >> 5;
    int v = (i < N_NODES) ? g_deg[i] : 0;
    int x = v;
    #pragma unroll
    for (int d = 1; d < 32; d <<= 1) {
        int t = __shfl_up_sync(0xFFFFFFFFu, x, d);
        if (lane >= d) x += t;
    }
    if (lane == 31) wsum[warp] = x;
    __syncthreads();
    if (tid < 32) {
        int w = wsum[tid];
        #pragma unroll
        for (int d = 1; d < 32; d <<= 1) {
            int t = __shfl_up_sync(0xFFFFFFFFu, w, d);
            if (tid >= d) w += t;
        }
        wsum[tid] = w;
    }
    __syncthreads();
    int excl = x - v + (warp ? wsum[warp - 1] : 0);
    if (i < N_NODES) g_off[i] = excl;
    if (tid == 0) g_bsum[blockIdx.x] = wsum[31];
}

__global__ void scan2_kernel() {   // 1 block, 64 threads
    __shared__ int ws[2];
    int tid = threadIdx.x, lane = tid & 31, warp = tid >> 5;
    int v = (tid < SCAN_BLOCKS) ? g_bsum[tid] : 0;
    int x = v;
    #pragma unroll
    for (int d = 1; d < 32; d <<= 1) {
        int t = __shfl_up_sync(0xFFFFFFFFu, x, d);
        if (lane >= d) x += t;
    }
    if (lane == 31) ws[warp] = x;
    __syncthreads();
    int excl = x - v + (warp ? ws[0] : 0);
    if (tid < SCAN_BLOCKS) g_bsum[tid] = excl;
    if (tid == SCAN_BLOCKS - 1) g_off[N_NODES] = excl + v;   // == N_EDGES
}

__global__ __launch_bounds__(1024) void scan3_kernel() {   // add offsets + dinv
    int i = blockIdx.x * 1024 + threadIdx.x;
    if (i < N_NODES) {
        g_off[i] += g_bsum[blockIdx.x];
        g_dinv[i] = rsqrtf((float)(g_deg[i] + 1));  // +1 self loop
    }
}

__global__ void fill_kernel(const int* __restrict__ ei) {
    int e = blockIdx.x * blockDim.x + threadIdx.x;
    if (e < N_EDGES) {
        int c = ei[N_EDGES + e];
        int r = ei[e];
        if (c >= 0 && c < N_NODES && r >= 0 && r < N_NODES) {
            int p = atomicAdd(&g_cur[c], 1);
            g_ebuf[g_off[c] + p] = r;
        }
    }
}

// ------------------- tensor-core GEMM via mma.sync (baseline PTX, HMMA) -----
// g_T = act(src) @ W. 3 bf16 passes: hi*Wh + mid*Wh + hi*Wm, fp32 accum.
// Block: 128 M-rows, 8 warps (warp = m16 x FOUT). K chunked by 64.
__device__ __forceinline__ void mma_bf16(float* c, const uint32_t* a,
                                         uint32_t b0, uint32_t b1) {
    asm volatile(
        "mma.sync.aligned.m16n8k16.row.col.f32.bf16.bf16.f32 "
        "{%0,%1,%2,%3}, {%4,%5,%6,%7}, {%8,%9}, {%0,%1,%2,%3};\n"
        : "+f"(c[0]), "+f"(c[1]), "+f"(c[2]), "+f"(c[3])
        : "r"(a[0]), "r"(a[1]), "r"(a[2]), "r"(a[3]), "r"(b0), "r"(b1));
}

template <int FOUT, bool RELU_IN, bool SRC_EXT, int L>
__global__ __launch_bounds__(256, 2) void gemm_mma(const float* __restrict__ X, int n)
{
    constexpr int NF = FOUT / 8;          // B fragments per warp (16 or 8)
    constexpr int ROWB = 72;              // padded row: 64 data + 8 pad bf16 (144B: rows 4 banks apart)
    __shared__ __nv_bfloat16 sA[128 * ROWB];
    __shared__ __nv_bfloat16 sB[FOUT * ROWB];
    const float* __restrict__ src = SRC_EXT ? X : (const float*)g_H;
    int m0 = blockIdx.x * 128;
    int t = threadIdx.x;
    int lane = t & 31, wid = t >> 5;

    float acc[NF][4];
    #pragma unroll
    for (int f = 0; f < NF; f++)
        #pragma unroll
        for (int c = 0; c < 4; c++) acc[f][c] = 0.f;

    #pragma unroll
    for (int pass = 0; pass < 3; pass++) {
        const bool a_hi = (pass != 1);
        const __nv_bfloat16* __restrict__ Wsp = (pass == 2) ? g_Wm[L] : g_Wh[L];
        #pragma unroll
        for (int kc = 0; kc < 2; kc++) {
            __syncthreads();
            // stage A chunk: 128 rows x 64 cols (split/convert, relu fused)
            #pragma unroll
            for (int i = 0; i < 8; i++) {
                int idx = t + i * 256;                 // 0..2047 float4 groups
                int row = idx >> 4, c4 = idx & 15;
                int gr = m0 + row;
                float4 v = make_float4(0.f, 0.f, 0.f, 0.f);
                if (gr < n) v = *(const float4*)&src[(size_t)gr * 128 + kc * 64 + c4 * 4];
                if (RELU_IN) {
                    v.x = fmaxf(v.x, 0.f); v.y = fmaxf(v.y, 0.f);
                    v.z = fmaxf(v.z, 0.f); v.w = fmaxf(v.w, 0.f);
                }
                __nv_bfloat16 h0 = __float2bfloat16(v.x), h1 = __float2bfloat16(v.y);
                __nv_bfloat16 h2 = __float2bfloat16(v.z), h3 = __float2bfloat16(v.w);
                __nv_bfloat16 o0, o1, o2, o3;
                if (a_hi) { o0 = h0; o1 = h1; o2 = h2; o3 = h3; }
                else {
                    o0 = __float2bfloat16(v.x - __bfloat162float(h0));
                    o1 = __float2bfloat16(v.y - __bfloat162float(h1));
                    o2 = __float2bfloat16(v.z - __bfloat162float(h2));
                    o3 = __float2bfloat16(v.w - __bfloat162float(h3));
                }
                uint32_t lo = ((uint32_t)__bfloat16_as_ushort(o1) << 16) | __bfloat16_as_ushort(o0);
                uint32_t hi = ((uint32_t)__bfloat16_as_ushort(o3) << 16) | __bfloat16_as_ushort(o2);
                *(uint2*)&sA[row * ROWB + c4 * 4] = make_uint2(lo, hi);
            }
            // stage B chunk: FOUT rows (n) x 64 cols (k) from pre-split bf16
            #pragma unroll
            for (int i = 0; i < FOUT / 16; i++) {
                int idx = t + i * 256;                 // FOUT*16 groups
                int nn = idx >> 4, c4 = idx & 15;
                uint2 w2 = *(const uint2*)&Wsp[nn * 128 + kc * 64 + c4 * 4];
                *(uint2*)&sB[nn * ROWB + c4 * 4] = w2;
            }
            __syncthreads();
            // 4 k16 steps
            #pragma unroll
            for (int ks = 0; ks < 4; ks++) {
                uint32_t a[4];
                int a_row = wid * 16 + (lane >> 2);
                int abase = a_row * ROWB + ks * 16 + (lane & 3) * 2;
                a[0] = *(const uint32_t*)&sA[abase];
                a[1] = *(const uint32_t*)&sA[abase + 8 * ROWB];
                a[2] = *(const uint32_t*)&sA[abase + 8];
                a[3] = *(const uint32_t*)&sA[abase + 8 * ROWB + 8];
                #pragma unroll
                for (int f = 0; f < NF; f++) {
                    int nb = f * 8 + (lane >> 2);
                    int bbase = nb * ROWB + ks * 16 + (lane & 3) * 2;
                    uint32_t b0 = *(const uint32_t*)&sB[bbase];
                    uint32_t b1 = *(const uint32_t*)&sB[bbase + 8];
                    mma_bf16(acc[f], a, b0, b1);
                }
            }
        }
    }

    // epilogue: each thread owns rows (lane/4, +8) of its warp tile
    int row0 = m0 + wid * 16 + (lane >> 2);
    int row1 = row0 + 8;
    #pragma unroll
    for (int f = 0; f < NF; f++) {
        int col = f * 8 + (lane & 3) * 2;
        if (row0 < n) *(float2*)&g_T[(size_t)row0 * FOUT + col] = make_float2(acc[f][0], acc[f][1]);
        if (row1 < n) *(float2*)&g_T[(size_t)row1 * FOUT + col] = make_float2(acc[f][2], acc[f][3]);
    }
}

// ------------------- Aggregation: g_H[i] = b + dinv_i^2*T[i] + sum_e dinv_r*dinv_i*T[r]
template <int F>
__global__ __launch_bounds__(256) void agg_kernel(const float* __restrict__ bias)
{
    int i = (blockIdx.x * blockDim.x + threadIdx.x) >> 5;
    if (i >= N_NODES) return;
    int lane = threadIdx.x & 31;
    constexpr int V = F / 32;  // 4 or 2
    float dii = g_dinv[i];
    float acc[V];
    {
        const float* Ti = g_T + (size_t)i * F + lane * V;
        float dii2 = dii * dii;
        #pragma unroll
        for (int c = 0; c < V; c++) acc[c] = bias[lane * V + c] + dii2 * Ti[c];
    }
    int s = g_off[i], e = g_off[i + 1];
    int p = s;
    for (; p + 2 <= e; p += 2) {
        int r0 = g_ebuf[p], r1 = g_ebuf[p + 1];
        float w0 = dii * g_dinv[r0], w1 = dii * g_dinv[r1];
        const float* T0 = g_T + (size_t)r0 * F + lane * V;
        const float* T1 = g_T + (size_t)r1 * F + lane * V;
        if (V == 4) {
            float4 a = *(const float4*)T0;
            float4 b = *(const float4*)T1;
            acc[0] += w0 * a.x; acc[1] += w0 * a.y;
            acc[2 % V] += w0 * a.z; acc[3 % V] += w0 * a.w;
            acc[0] += w1 * b.x; acc[1] += w1 * b.y;
            acc[2 % V] += w1 * b.z; acc[3 % V] += w1 * b.w;
        } else {
            float2 a = *(const float2*)T0;
            float2 b = *(const float2*)T1;
            acc[0] += w0 * a.x; acc[1] += w0 * a.y;
            acc[0] += w1 * b.x; acc[1] += w1 * b.y;
        }
    }
    if (p < e) {
        int r = g_ebuf[p];
        float w = dii * g_dinv[r];
        const float* Tr = g_T + (size_t)r * F + lane * V;
        if (V == 4) {
            float4 a = *(const float4*)Tr;
            acc[0] += w * a.x; acc[1] += w * a.y;
            acc[2 % V] += w * a.z; acc[3 % V] += w * a.w;
        } else {
            float2 a = *(const float2*)Tr;
            acc[0] += w * a.x; acc[1] += w * a.y;
        }
    }
    float* Hi = g_H + (size_t)i * F + lane * V;
    #pragma unroll
    for (int c = 0; c < V; c++) Hi[c] = acc[c];
}

// ------------------- mean pool over sorted batch ids (input relu'd here) -----
__global__ void pool_kernel(const int* __restrict__ batch)
{
    int c = threadIdx.x & 63;   // channel
    int sub = threadIdx.x >> 6; // 0..3
    int n0 = blockIdx.x * 512;
    float acc = 0.f; int cur = -1; int cnt = 0;
    for (int j = sub; j < 512; j += 4) {
        int node = n0 + j;
        if (node >= N_NODES) break;
        int b = batch[node];
        if (b < 0 || b >= N_GRAPHS) continue;
        if (b != cur) {
            if (cur >= 0) {
                atomicAdd(&g_pool[cur * 64 + c], acc);
                if (c == 0) atomicAdd(&g_cnt[cur], cnt);
            }
            cur = b; acc = 0.f; cnt = 0;
        }
        acc += fmaxf(g_H[(size_t)node * 64 + c], 0.f);
        cnt++;
    }
    if (cur >= 0) {
        atomicAdd(&g_pool[cur * 64 + c], acc);
        if (c == 0) atomicAdd(&g_cnt[cur], cnt);
    }
}

// ------------------- tiny MLP head -------------------
__global__ void fc1_kernel(const float* __restrict__ Wf1, const float* __restrict__ bf1) {
    int g = blockIdx.x; int j = threadIdx.x;  // grid 64, block 32
    float inv = 1.f / fmaxf((float)g_cnt[g], 1.f);
    float s = bf1[j];
    for (int k = 0; k < 64; k++) s += g_pool[g * 64 + k] * inv * Wf1[k * 32 + j];
    g_fc1[g * 32 + j] = fmaxf(s, 0.f);
}

__global__ void fc2_kernel(const float* __restrict__ Wf2, const float* __restrict__ bf2,
                           float* __restrict__ out) {
    int g = blockIdx.x; int o = threadIdx.x;  // grid 64, block 10
    float s = bf2[o];
    for (int j = 0; j < 32; j++) s += g_fc1[g * 32 + j] * Wf2[j * 10 + o];
    out[g * 10 + o] = s;
}

// ------------------- launch: kernel launches ONLY, no other CUDA API --------
extern "C" void kernel_launch(void* const* d_in, const int* in_sizes, int n_in,
                              void* d_out, int out_size)
{
    const float* x     = (const float*)d_in[0];
    const int*   ei    = (const int*)d_in[1];
    const int*   batch = (const int*)d_in[2];
    const float* W1  = (const float*)d_in[3];
    const float* b1  = (const float*)d_in[4];
    const float* W2  = (const float*)d_in[5];
    const float* b2  = (const float*)d_in[6];
    const float* W3  = (const float*)d_in[7];
    const float* b3  = (const float*)d_in[8];
    const float* Wf1 = (const float*)d_in[9];
    const float* bf1 = (const float*)d_in[10];
    const float* Wf2 = (const float*)d_in[11];
    const float* bf2 = (const float*)d_in[12];
    float* out = (float*)d_out;

    zero_kernel<<<(N_NODES + 255) / 256, 256>>>();
    prep_w_kernel<<<64, 256>>>(W1, W2, W3);

    // CSR build
    count_kernel<<<(N_EDGES + 255) / 256, 256>>>(ei);
    scan1_kernel<<<SCAN_BLOCKS, 1024>>>();
    scan2_kernel<<<1, 64>>>();
    scan3_kernel<<<SCAN_BLOCKS, 1024>>>();
    fill_kernel<<<(N_EDGES + 255) / 256, 256>>>(ei);

    int mma_blocks = (N_NODES + 127) / 128;   // 391
    int agg_blocks = (N_NODES * 32 + 255) / 256;

    // layer 1: 128 -> 128 (external input)
    gemm_mma<128, false, true, 0><<<mma_blocks, 256>>>(x, N_NODES);
    agg_kernel<128><<<agg_blocks, 256>>>(b1);
    // layer 2: 128 -> 128 (g_H input, relu)
    gemm_mma<128, true, false, 1><<<mma_blocks, 256>>>(nullptr, N_NODES);
    agg_kernel<128><<<agg_blocks, 256>>>(b2);
    // layer 3: 128 -> 64 (g_H input, relu)
    gemm_mma<64, true, false, 2><<<mma_blocks, 256>>>(nullptr, N_NODES);
    agg_kernel<64><<<agg_blocks, 256>>>(b3);

    // mean pool (relu fused) + MLP head
    pool_kernel<<<(N_NODES + 511) / 512, 256>>>(batch);
    fc1_kernel<<<N_GRAPHS, 32>>>(Wf1, bf1);
    fc2_kernel<<<N_GRAPHS, 10>>>(Wf2, bf2, out);
}

// round 14
// speedup vs baseline: 1.7398x; 1.0907x over previous
#include <cuda_runtime.h>
#include <cuda_bf16.h>
#include <math.h>
#include <stdint.h>

#define N_NODES 50000
#define N_PAD   50048                    // padded row count (multiple of 128)
#define N_EDGES 600000
#define N_GRAPHS 64
#define SCAN_BLOCKS ((N_NODES + 1023) / 1024)   // 49

// ------------------- scratch (no allocation allowed) -------------------
__device__ float g_T[N_NODES * 128];     // GEMM output (transformed features)
__device__ float g_H[N_NODES * 64];      // layer-3 agg output (for pool)
__device__ __nv_bfloat16 g_Ah[N_PAD * 128];  // split GEMM input, hi
__device__ __nv_bfloat16 g_Am[N_PAD * 128];  // split GEMM input, mid
__device__ float g_dinv[N_NODES];
__device__ int   g_deg[N_NODES];
__device__ int   g_off[N_NODES + 1];
__device__ int   g_cur[N_NODES];
__device__ int   g_ebuf[N_EDGES];        // CSR: source row per slot (by destination)
__device__ int   g_bsum[64];             // scan block sums
__device__ float g_pool[N_GRAPHS * 64];
__device__ int   g_cnt[N_GRAPHS];
// split weights, transposed to [n][k] bf16 (hi/mid)
__device__ __nv_bfloat16 g_Wh[3][128 * 128];
__device__ __nv_bfloat16 g_Wm[3][128 * 128];

__device__ __forceinline__ uint32_t pack_bf16(__nv_bfloat16 a, __nv_bfloat16 b) {
    return ((uint32_t)__bfloat16_as_ushort(b) << 16) | __bfloat16_as_ushort(a);
}

// ------------------- zero init -------------------
__global__ void zero_kernel() {
    int i = blockIdx.x * blockDim.x + threadIdx.x;
    if (i < N_NODES) { g_deg[i] = 0; g_cur[i] = 0; }
    if (i < N_GRAPHS * 64) g_pool[i] = 0.f;
    if (i < N_GRAPHS) g_cnt[i] = 0;
}

// ------------------- prep: split x -> Ah/Am, split+transpose W -------------
__global__ void prep_kernel(const float* __restrict__ x,
                            const float* __restrict__ W1,
                            const float* __restrict__ W2,
                            const float* __restrict__ W3) {
    int t = blockIdx.x * blockDim.x + threadIdx.x;
    if (t < N_NODES * 32) {              // 4 elems per thread
        float4 v = ((const float4*)x)[t];
        __nv_bfloat16 h0 = __float2bfloat16(v.x), h1 = __float2bfloat16(v.y);
        __nv_bfloat16 h2 = __float2bfloat16(v.z), h3 = __float2bfloat16(v.w);
        ((uint2*)g_Ah)[t] = make_uint2(pack_bf16(h0, h1), pack_bf16(h2, h3));
        ((uint2*)g_Am)[t] = make_uint2(
            pack_bf16(__float2bfloat16(v.x - __bfloat162float(h0)),
                      __float2bfloat16(v.y - __bfloat162float(h1))),
            pack_bf16(__float2bfloat16(v.z - __bfloat162float(h2)),
                      __float2bfloat16(v.w - __bfloat162float(h3))));
    }
    if (t < 128 * 128) {
        int n = t >> 7, k = t & 127;
        float v1 = W1[k * 128 + n];
        __nv_bfloat16 h1 = __float2bfloat16(v1);
        g_Wh[0][n * 128 + k] = h1;
        g_Wm[0][n * 128 + k] = __float2bfloat16(v1 - __bfloat162float(h1));
        float v2 = W2[k * 128 + n];
        __nv_bfloat16 h2 = __float2bfloat16(v2);
        g_Wh[1][n * 128 + k] = h2;
        g_Wm[1][n * 128 + k] = __float2bfloat16(v2 - __bfloat162float(h2));
        if (n < 64) {
            float v3 = W3[k * 64 + n];
            __nv_bfloat16 h3 = __float2bfloat16(v3);
            g_Wh[2][n * 128 + k] = h3;
            g_Wm[2][n * 128 + k] = __float2bfloat16(v3 - __bfloat162float(h3));
        }
    }
}

// ------------------- CSR build (edge_index is int32) -------------------
__global__ void count_kernel(const int* __restrict__ ei) {
    int e = blockIdx.x * blockDim.x + threadIdx.x;
    if (e < N_EDGES) {
        int c = ei[N_EDGES + e];
        if (c >= 0 && c < N_NODES) atomicAdd(&g_deg[c], 1);
    }
}

__global__ __launch_bounds__(1024) void scan1_kernel() {
    __shared__ int wsum[32];
    int tid = threadIdx.x;
    int i = blockIdx.x * 1024 + tid;
    int lane = tid & 31, warp = tid >> 5;
    int v = (i < N_NODES) ? g_deg[i] : 0;
    int x = v;
    #pragma unroll
    for (int d = 1; d < 32; d <<= 1) {
        int t = __shfl_up_sync(0xFFFFFFFFu, x, d);
        if (lane >= d) x += t;
    }
    if (lane == 31) wsum[warp] = x;
    __syncthreads();
    if (tid < 32) {
        int w = wsum[tid];
        #pragma unroll
        for (int d = 1; d < 32; d <<= 1) {
            int t = __shfl_up_sync(0xFFFFFFFFu, w, d);
            if (tid >= d) w += t;
        }
        wsum[tid] = w;
    }
    __syncthreads();
    int excl = x - v + (warp ? wsum[warp - 1] : 0);
    if (i < N_NODES) g_off[i] = excl;
    if (tid == 0) g_bsum[blockIdx.x] = wsum[31];
}

__global__ void scan2_kernel() {   // 1 block, 64 threads
    __shared__ int ws[2];
    int tid = threadIdx.x, lane = tid & 31, warp = tid >> 5;
    int v = (tid < SCAN_BLOCKS) ? g_bsum[tid] : 0;
    int x = v;
    #pragma unroll
    for (int d = 1; d < 32; d <<= 1) {
        int t = __shfl_up_sync(0xFFFFFFFFu, x, d);
        if (lane >= d) x += t;
    }
    if (lane == 31) ws[warp] = x;
    __syncthreads();
    int excl = x - v + (warp ? ws[0] : 0);
    if (tid < SCAN_BLOCKS) g_bsum[tid] = excl;
    if (tid == SCAN_BLOCKS - 1) g_off[N_NODES] = excl + v;   // == N_EDGES
}

__global__ __launch_bounds__(1024) void scan3_kernel() {   // add offsets + dinv
    int i = blockIdx.x * 1024 + threadIdx.x;
    if (i < N_NODES) {
        g_off[i] += g_bsum[blockIdx.x];
        g_dinv[i] = rsqrtf((float)(g_deg[i] + 1));  // +1 self loop
    }
}

__global__ void fill_kernel(const int* __restrict__ ei) {
    int e = blockIdx.x * blockDim.x + threadIdx.x;
    if (e < N_EDGES) {
        int c = ei[N_EDGES + e];
        int r = ei[e];
        if (c >= 0 && c < N_NODES && r >= 0 && r < N_NODES) {
            int p = atomicAdd(&g_cur[c], 1);
            g_ebuf[g_off[c] + p] = r;
        }
    }
}

// ------------------- tensor-core GEMM via mma.sync (HMMA) -------------------
// g_T = A @ W where A is pre-split bf16 (g_Ah/g_Am). 3 passes per k-chunk:
// Ah*Wh, Ah*Wm, Am*Wh (A staged twice, B thrice). fp32 accum.
__device__ __forceinline__ void mma_bf16(float* c, const uint32_t* a,
                                         uint32_t b0, uint32_t b1) {
    asm volatile(
        "mma.sync.aligned.m16n8k16.row.col.f32.bf16.bf16.f32 "
        "{%0,%1,%2,%3}, {%4,%5,%6,%7}, {%8,%9}, {%0,%1,%2,%3};\n"
        : "+f"(c[0]), "+f"(c[1]), "+f"(c[2]), "+f"(c[3])
        : "r"(a[0]), "r"(a[1]), "r"(a[2]), "r"(a[3]), "r"(b0), "r"(b1));
}

template <int FOUT, int L>
__global__ __launch_bounds__(256, 2) void gemm_mma(int n)
{
    constexpr int NF = FOUT / 8;          // B fragments per warp
    constexpr int ROWB = 72;              // 64 data + 8 pad bf16 (144B rows)
    __shared__ __nv_bfloat16 sA[128 * ROWB];
    __shared__ __nv_bfloat16 sB[FOUT * ROWB];
    int m0 = blockIdx.x * 128;
    int t = threadIdx.x;
    int lane = t & 31, wid = t >> 5;

    float acc[NF][4];
    #pragma unroll
    for (int f = 0; f < NF; f++)
        #pragma unroll
        for (int c = 0; c < 4; c++) acc[f][c] = 0.f;

    #pragma unroll
    for (int kc = 0; kc < 2; kc++) {
        #pragma unroll
        for (int pass = 0; pass < 3; pass++) {
            __syncthreads();
            // stage A (only when it changes: pass 0 -> Ah, pass 2 -> Am)
            if (pass != 1) {
                const __nv_bfloat16* __restrict__ Asrc = (pass == 0) ? g_Ah : g_Am;
                #pragma unroll
                for (int i = 0; i < 4; i++) {        // 1024 uint4 groups
                    int idx = t + i * 256;
                    int row = idx >> 3, g8 = idx & 7;
                    uint4 v = *(const uint4*)&Asrc[(size_t)(m0 + row) * 128 + kc * 64 + g8 * 8];
                    *(uint4*)&sA[row * ROWB + g8 * 8] = v;
                }
            }
            // stage B: pass 1 -> Wm, else Wh
            {
                const __nv_bfloat16* __restrict__ Wsp = (pass == 1) ? g_Wm[L] : g_Wh[L];
                #pragma unroll
                for (int i = 0; i < FOUT / 32; i++) { // FOUT*8 uint4 groups
                    int idx = t + i * 256;
                    int nn = idx >> 3, g8 = idx & 7;
                    uint4 v = *(const uint4*)&Wsp[nn * 128 + kc * 64 + g8 * 8];
                    *(uint4*)&sB[nn * ROWB + g8 * 8] = v;
                }
            }
            __syncthreads();
            #pragma unroll
            for (int ks = 0; ks < 4; ks++) {
                uint32_t a[4];
                int a_row = wid * 16 + (lane >> 2);
                int abase = a_row * ROWB + ks * 16 + (lane & 3) * 2;
                a[0] = *(const uint32_t*)&sA[abase];
                a[1] = *(const uint32_t*)&sA[abase + 8 * ROWB];
                a[2] = *(const uint32_t*)&sA[abase + 8];
                a[3] = *(const uint32_t*)&sA[abase + 8 * ROWB + 8];
                #pragma unroll
                for (int f = 0; f < NF; f++) {
                    int nb = f * 8 + (lane >> 2);
                    int bbase = nb * ROWB + ks * 16 + (lane & 3) * 2;
                    uint32_t b0 = *(const uint32_t*)&sB[bbase];
                    uint32_t b1 = *(const uint32_t*)&sB[bbase + 8];
                    mma_bf16(acc[f], a, b0, b1);
                }
            }
        }
    }

    int row0 = m0 + wid * 16 + (lane >> 2);
    int row1 = row0 + 8;
    #pragma unroll
    for (int f = 0; f < NF; f++) {
        int col = f * 8 + (lane & 3) * 2;
        if (row0 < n) *(float2*)&g_T[(size_t)row0 * FOUT + col] = make_float2(acc[f][0], acc[f][1]);
        if (row1 < n) *(float2*)&g_T[(size_t)row1 * FOUT + col] = make_float2(acc[f][2], acc[f][3]);
    }
}

// ------------------- Aggregation -------------------
// acc = b + dinv_i^2*T[i] + sum_e dinv_r*dinv_i*T[r]
// SPLIT_OUT: write relu(acc) split to g_Ah/g_Am (feeds next GEMM)
// else:      write acc fp32 to g_H (layer 3, feeds pool)
template <int F, bool SPLIT_OUT>
__global__ __launch_bounds__(256) void agg_kernel(const float* __restrict__ bias)
{
    int i = (blockIdx.x * blockDim.x + threadIdx.x) >> 5;
    if (i >= N_NODES) return;
    int lane = threadIdx.x & 31;
    constexpr int V = F / 32;  // 4 or 2
    float dii = g_dinv[i];
    float acc[V];
    {
        const float* Ti = g_T + (size_t)i * F + lane * V;
        float dii2 = dii * dii;
        #pragma unroll
        for (int c = 0; c < V; c++) acc[c] = bias[lane * V + c] + dii2 * Ti[c];
    }
    int s = g_off[i], e = g_off[i + 1];
    int p = s;
    for (; p + 2 <= e; p += 2) {
        int r0 = g_ebuf[p], r1 = g_ebuf[p + 1];
        float w0 = dii * g_dinv[r0], w1 = dii * g_dinv[r1];
        const float* T0 = g_T + (size_t)r0 * F + lane * V;
        const float* T1 = g_T + (size_t)r1 * F + lane * V;
        if (V == 4) {
            float4 a = *(const float4*)T0;
            float4 b = *(const float4*)T1;
            acc[0] += w0 * a.x; acc[1] += w0 * a.y;
            acc[2 % V] += w0 * a.z; acc[3 % V] += w0 * a.w;
            acc[0] += w1 * b.x; acc[1] += w1 * b.y;
            acc[2 % V] += w1 * b.z; acc[3 % V] += w1 * b.w;
        } else {
            float2 a = *(const float2*)T0;
            float2 b = *(const float2*)T1;
            acc[0] += w0 * a.x; acc[1] += w0 * a.y;
            acc[0] += w1 * b.x; acc[1] += w1 * b.y;
        }
    }
    if (p < e) {
        int r = g_ebuf[p];
        float w = dii * g_dinv[r];
        const float* Tr = g_T + (size_t)r * F + lane * V;
        if (V == 4) {
            float4 a = *(const float4*)Tr;
            acc[0] += w * a.x; acc[1] += w * a.y;
            acc[2 % V] += w * a.z; acc[3 % V] += w * a.w;
        } else {
            float2 a = *(const float2*)Tr;
            acc[0] += w * a.x; acc[1] += w * a.y;
        }
    }
    if (SPLIT_OUT) {
        // relu + bf16 split, write hi/mid (V==4 path used for F=128)
        #pragma unroll
        for (int c = 0; c < V; c++) acc[c] = fmaxf(acc[c], 0.f);
        __nv_bfloat16 h[V], m[V];
        #pragma unroll
        for (int c = 0; c < V; c++) {
            h[c] = __float2bfloat16(acc[c]);
            m[c] = __float2bfloat16(acc[c] - __bfloat162float(h[c]));
        }
        if (V == 4) {
            *(uint2*)&g_Ah[(size_t)i * F + lane * 4] =
                make_uint2(pack_bf16(h[0], h[1]), pack_bf16(h[2 % V], h[3 % V]));
            *(uint2*)&g_Am[(size_t)i * F + lane * 4] =
                make_uint2(pack_bf16(m[0], m[1]), pack_bf16(m[2 % V], m[3 % V]));
        } else {
            *(uint32_t*)&g_Ah[(size_t)i * F + lane * 2] = pack_bf16(h[0], h[1]);
            *(uint32_t*)&g_Am[(size_t)i * F + lane * 2] = pack_bf16(m[0], m[1]);
        }
    } else {
        float* Hi = g_H + (size_t)i * F + lane * V;
        #pragma unroll
        for (int c = 0; c < V; c++) Hi[c] = acc[c];
    }
}

// ------------------- mean pool over sorted batch ids (relu fused) -----------
__global__ void pool_kernel(const int* __restrict__ batch)
{
    int c = threadIdx.x & 63;   // channel
    int sub = threadIdx.x >> 6; // 0..3
    int n0 = blockIdx.x * 512;
    float acc = 0.f; int cur = -1; int cnt = 0;
    for (int j = sub; j < 512; j += 4) {
        int node = n0 + j;
        if (node >= N_NODES) break;
        int b = batch[node];
        if (b < 0 || b >= N_GRAPHS) continue;
        if (b != cur) {
            if (cur >= 0) {
                atomicAdd(&g_pool[cur * 64 + c], acc);
                if (c == 0) atomicAdd(&g_cnt[cur], cnt);
            }
            cur = b; acc = 0.f; cnt = 0;
        }
        acc += fmaxf(g_H[(size_t)node * 64 + c], 0.f);
        cnt++;
    }
    if (cur >= 0) {
        atomicAdd(&g_pool[cur * 64 + c], acc);
        if (c == 0) atomicAdd(&g_cnt[cur], cnt);
    }
}

// ------------------- fused MLP head -------------------
__global__ void head_kernel(const float* __restrict__ Wf1, const float* __restrict__ bf1,
                            const float* __restrict__ Wf2, const float* __restrict__ bf2,
                            float* __restrict__ out) {
    __shared__ float h[32];
    int g = blockIdx.x; int j = threadIdx.x;  // grid 64, block 32
    float inv = 1.f / fmaxf((float)g_cnt[g], 1.f);
    float s = bf1[j];
    for (int k = 0; k < 64; k++) s += g_pool[g * 64 + k] * inv * Wf1[k * 32 + j];
    h[j] = fmaxf(s, 0.f);
    __syncwarp();
    if (j < 10) {
        float o = bf2[j];
        #pragma unroll
        for (int k = 0; k < 32; k++) o += h[k] * Wf2[k * 10 + j];
        out[g * 10 + j] = o;
    }
}

// ------------------- launch: kernel launches ONLY, no other CUDA API --------
extern "C" void kernel_launch(void* const* d_in, const int* in_sizes, int n_in,
                              void* d_out, int out_size)
{
    const float* x     = (const float*)d_in[0];
    const int*   ei    = (const int*)d_in[1];
    const int*   batch = (const int*)d_in[2];
    const float* W1  = (const float*)d_in[3];
    const float* b1  = (const float*)d_in[4];
    const float* W2  = (const float*)d_in[5];
    const float* b2  = (const float*)d_in[6];
    const float* W3  = (const float*)d_in[7];
    const float* b3  = (const float*)d_in[8];
    const float* Wf1 = (const float*)d_in[9];
    const float* bf1 = (const float*)d_in[10];
    const float* Wf2 = (const float*)d_in[11];
    const float* bf2 = (const float*)d_in[12];
    float* out = (float*)d_out;

    zero_kernel<<<(N_NODES + 255) / 256, 256>>>();
    prep_kernel<<<(N_NODES * 32 + 255) / 256, 256>>>(x, W1, W2, W3);

    // CSR build
    count_kernel<<<(N_EDGES + 255) / 256, 256>>>(ei);
    scan1_kernel<<<SCAN_BLOCKS, 1024>>>();
    scan2_kernel<<<1, 64>>>();
    scan3_kernel<<<SCAN_BLOCKS, 1024>>>();
    fill_kernel<<<(N_EDGES + 255) / 256, 256>>>(ei);

    int mma_blocks = (N_NODES + 127) / 128;   // 391
    int agg_blocks = (N_NODES * 32 + 255) / 256;

    // layer 1: 128 -> 128
    gemm_mma<128, 0><<<mma_blocks, 256>>>(N_NODES);
    agg_kernel<128, true><<<agg_blocks, 256>>>(b1);   // -> split bf16
    // layer 2: 128 -> 128
    gemm_mma<128, 1><<<mma_blocks, 256>>>(N_NODES);
    agg_kernel<128, true><<<agg_blocks, 256>>>(b2);   // -> split bf16
    // layer 3: 128 -> 64
    gemm_mma<64, 2><<<mma_blocks, 256>>>(N_NODES);
    agg_kernel<64, false><<<agg_blocks, 256>>>(b3);   // -> fp32 g_H

    // mean pool (relu fused) + fused MLP head
    pool_kernel<<<(N_NODES + 511) / 512, 256>>>(batch);
    head_kernel<<<N_GRAPHS, 32>>>(Wf1, bf1, Wf2, bf2, out);
}